// round 17
// baseline (speedup 1.0000x reference)
#include <cuda_runtime.h>

#define NTH  256

struct Params { const float* p[27]; };

// Exact leaky-relu slope 0.0025: rr(v) = max(v, 0.0025*v).
__device__ __forceinline__ float rr(float v) {
    return fmaxf(v, 0.0025f * v);
}

// ---- constant-memory layout (floats); W/b offsets 16B-aligned for LDC.128 ----
// W_in stored TRANSPOSED: c_s[j*8+i] = W_in[i][j]
#define O_WIN_T  0      // 64
#define O_B_IN   64     // 8
#define O_W_H1   72     // [8][4] row-major, 32
#define O_B_H1   104    // 4
#define O_W_H2   108
#define O_B_H2   124
#define O_W_H3   128
#define O_B_H3   144
#define O_W_H4   148
#define O_B_H4   164
#define O_W_H5   168
#define O_B_H5   184
#define O_W_EN   188    // 4
#define O_B_EN   192    // 1 (+3 pad)
#define O_W_H6   196    // 4
#define O_B_H6   200    // 4
#define O_W_H7   204
#define O_B_H7   220
#define O_W_H8   224
#define O_B_H8   240
#define O_W_H9   244
#define O_B_H9   260
#define O_W_HA   264
#define O_B_HA   280
#define O_W_DE   284    // [4][8] row-major, 32
#define O_B_DE   316    // 8
#define S_TOTAL  324

__constant__ float c_s[S_TOTAL];
__device__   float g_stage[S_TOTAL];   // static scratch (no allocation)

// Fully parallel gather: one thread per destination slot, one LDG + one STG each.
__global__ void gather_weights(Params P) {
    int i = threadIdx.x;
    if (i >= S_TOTAL) return;

    float v = 0.f;                       // pad slots (193..195) -> 0
    if (i < O_B_IN) {
        int j = i >> 3, ii = i & 7;
        v = P.p[1][ii * 8 + j];          // transposed W_in
    } else {
        const short off[26] = {O_B_IN,O_W_H1,O_B_H1,O_W_H2,O_B_H2,O_W_H3,O_B_H3,
                               O_W_H4,O_B_H4,O_W_H5,O_B_H5,O_W_EN,O_B_EN,O_W_H6,O_B_H6,
                               O_W_H7,O_B_H7,O_W_H8,O_B_H8,O_W_H9,O_B_H9,O_W_HA,O_B_HA,
                               O_W_DE,O_B_DE,S_TOTAL};
        const short cnt[25] = {8,32,4,16,4,16,4,16,4,16,4,4,1,4,4,16,4,16,4,16,4,16,4,32,8};
#pragma unroll
        for (int k = 0; k < 25; k++) {
            int rel = i - off[k];
            if (rel >= 0 && rel < cnt[k]) v = P.p[k + 2][rel];
        }
    }
    g_stage[i] = v;
}

__device__ __forceinline__ float4 ld4c(int off) {
    return *reinterpret_cast<const float4*>(c_s + off);
}

// 4x4 layer for 4 rows, j-vectorized, bias folded into the peeled i=0 FMA.
template<bool ACT, bool RESID>
__device__ __forceinline__ void lin44(int Woff, int boff,
                                      const float (&src)[4][4], float (&dst)[4][4]) {
    float4 b = ld4c(boff);
    float acc[4][4];
    {   // i = 0 peeled: acc = src0*w0 + (bias [+ dst for residual])
        float4 w = ld4c(Woff);
#pragma unroll
        for (int r = 0; r < 4; r++) {
            float a0 = RESID ? (dst[r][0] + b.x) : b.x;
            float a1 = RESID ? (dst[r][1] + b.y) : b.y;
            float a2 = RESID ? (dst[r][2] + b.z) : b.z;
            float a3 = RESID ? (dst[r][3] + b.w) : b.w;
            acc[r][0] = fmaf(src[r][0], w.x, a0);
            acc[r][1] = fmaf(src[r][0], w.y, a1);
            acc[r][2] = fmaf(src[r][0], w.z, a2);
            acc[r][3] = fmaf(src[r][0], w.w, a3);
        }
    }
#pragma unroll
    for (int i = 1; i < 4; i++) {
        float4 w = ld4c(Woff + 4 * i);
#pragma unroll
        for (int r = 0; r < 4; r++) {
            acc[r][0] = fmaf(src[r][i], w.x, acc[r][0]);
            acc[r][1] = fmaf(src[r][i], w.y, acc[r][1]);
            acc[r][2] = fmaf(src[r][i], w.z, acc[r][2]);
            acc[r][3] = fmaf(src[r][i], w.w, acc[r][3]);
        }
    }
#pragma unroll
    for (int r = 0; r < 4; r++)
#pragma unroll
        for (int j = 0; j < 4; j++)
            dst[r][j] = ACT ? rr(acc[r][j]) : acc[r][j];
}

template<bool GUARD>
__global__ __launch_bounds__(NTH)
void ann_fused_kernel(const float* __restrict__ xin, float* __restrict__ out, int N) {
    unsigned base = blockIdx.x * (4 * NTH) + threadIdx.x;

    // Per-stream base pointers; all row offsets below are compile-time
    // immediates (r*NTH*stride), so global accesses are LDG/STG [R+imm].
    const char* __restrict__ xb = reinterpret_cast<const char*>(xin) + (size_t)base * 32;
    char* __restrict__ eb = reinterpret_cast<char*>(out) + (size_t)base * 4;
    char* __restrict__ db = reinterpret_cast<char*>(out) + (size_t)N * 4 + (size_t)base * 32;

    // ---- load ALL 4 rows up front (8 x LDG.128 [R+imm], streaming) ----
    float4 A0[4], A1[4];
#pragma unroll
    for (int r = 0; r < 4; r++) {
        if (!GUARD || base + r * NTH < (unsigned)N) {
            A0[r] = __ldcs(reinterpret_cast<const float4*>(xb + r * (NTH * 32)));
            A1[r] = __ldcs(reinterpret_cast<const float4*>(xb + r * (NTH * 32) + 16));
        } else {
            A0[r] = make_float4(0.f,0.f,0.f,0.f);
            A1[r] = make_float4(0.f,0.f,0.f,0.f);
        }
    }

    // ---- fused in+h1, j-OUTER over the 8 hidden units ----
    float x[4][4];
    {
        float4 bh1 = ld4c(O_B_H1);
#pragma unroll
        for (int r = 0; r < 4; r++) {
            x[r][0]=bh1.x; x[r][1]=bh1.y; x[r][2]=bh1.z; x[r][3]=bh1.w;
        }
#pragma unroll
        for (int j = 0; j < 8; j++) {
            float bj = c_s[O_B_IN + j];
            float4 w0 = ld4c(O_WIN_T + j * 8);
            float4 w1 = ld4c(O_WIN_T + j * 8 + 4);
            float v[4];
#pragma unroll
            for (int r = 0; r < 4; r++) {
                float a = fmaf(A0[r].x, w0.x, bj);   // bias folded into first FMA
                a = fmaf(A0[r].y, w0.y, a);
                a = fmaf(A0[r].z, w0.z, a); a = fmaf(A0[r].w, w0.w, a);
                a = fmaf(A1[r].x, w1.x, a); a = fmaf(A1[r].y, w1.y, a);
                a = fmaf(A1[r].z, w1.z, a); a = fmaf(A1[r].w, w1.w, a);
                v[r] = rr(a);
            }
            float4 h = ld4c(O_W_H1 + j * 4);
#pragma unroll
            for (int r = 0; r < 4; r++) {
                x[r][0] = fmaf(v[r], h.x, x[r][0]);
                x[r][1] = fmaf(v[r], h.y, x[r][1]);
                x[r][2] = fmaf(v[r], h.z, x[r][2]);
                x[r][3] = fmaf(v[r], h.w, x[r][3]);
            }
        }
    }
    // A0/A1 dead from here.

    float t[4][4];

    // ---- encoder residual blocks ----
    lin44<true,  false>(O_W_H2, O_B_H2, x, t);
    lin44<false, true >(O_W_H3, O_B_H3, t, x);
    lin44<true,  false>(O_W_H4, O_B_H4, x, t);
    lin44<false, true >(O_W_H5, O_B_H5, t, x);

    // ---- encode (4 -> 1) + store ----
    float e[4];
    {
        float4 we = ld4c(O_W_EN);
        float be = c_s[O_B_EN];
#pragma unroll
        for (int r = 0; r < 4; r++) {
            float v = fmaf(x[r][0], we.x, be);
            v = fmaf(x[r][1], we.y, v);
            v = fmaf(x[r][2], we.z, v); v = fmaf(x[r][3], we.w, v);
            e[r] = rr(v);
        }
    }
#pragma unroll
    for (int r = 0; r < 4; r++) {
        if (!GUARD || base + r * NTH < (unsigned)N)
            __stcs(reinterpret_cast<float*>(eb + r * (NTH * 4)), e[r]);
    }

    // ---- h6 (1 -> 4) ----
    {
        float4 w6 = ld4c(O_W_H6);
        float4 b6 = ld4c(O_B_H6);
#pragma unroll
        for (int r = 0; r < 4; r++) {
            x[r][0] = rr(fmaf(e[r], w6.x, b6.x));
            x[r][1] = rr(fmaf(e[r], w6.y, b6.y));
            x[r][2] = rr(fmaf(e[r], w6.z, b6.z));
            x[r][3] = rr(fmaf(e[r], w6.w, b6.w));
        }
    }

    // ---- decoder residual blocks ----
    lin44<true,  false>(O_W_H7, O_B_H7, x, t);
    lin44<false, true >(O_W_H8, O_B_H8, t, x);
    lin44<true,  false>(O_W_H9, O_B_H9, x, t);
    lin44<false, true >(O_W_HA, O_B_HA, t, x);

    // ---- decode (4 -> 8) + store, 2 rows at a time; biases hoisted ----
    float4 bd0 = ld4c(O_B_DE);
    float4 bd1 = ld4c(O_B_DE + 4);
#pragma unroll
    for (int pp = 0; pp < 2; pp++) {
        float da[8], db_[8];
        {   // i = 0 peeled: acc = x0*w + bias
            float4 w0 = ld4c(O_W_DE);
            float4 w1 = ld4c(O_W_DE + 4);
            float va = x[2*pp][0], vb = x[2*pp+1][0];
            da[0] = fmaf(va, w0.x, bd0.x); db_[0] = fmaf(vb, w0.x, bd0.x);
            da[1] = fmaf(va, w0.y, bd0.y); db_[1] = fmaf(vb, w0.y, bd0.y);
            da[2] = fmaf(va, w0.z, bd0.z); db_[2] = fmaf(vb, w0.z, bd0.z);
            da[3] = fmaf(va, w0.w, bd0.w); db_[3] = fmaf(vb, w0.w, bd0.w);
            da[4] = fmaf(va, w1.x, bd1.x); db_[4] = fmaf(vb, w1.x, bd1.x);
            da[5] = fmaf(va, w1.y, bd1.y); db_[5] = fmaf(vb, w1.y, bd1.y);
            da[6] = fmaf(va, w1.z, bd1.z); db_[6] = fmaf(vb, w1.z, bd1.z);
            da[7] = fmaf(va, w1.w, bd1.w); db_[7] = fmaf(vb, w1.w, bd1.w);
        }
#pragma unroll
        for (int i = 1; i < 4; i++) {
            float4 w0 = ld4c(O_W_DE + i * 8);
            float4 w1 = ld4c(O_W_DE + i * 8 + 4);
            float va = x[2*pp][i], vb = x[2*pp+1][i];
            da[0] = fmaf(va, w0.x, da[0]); db_[0] = fmaf(vb, w0.x, db_[0]);
            da[1] = fmaf(va, w0.y, da[1]); db_[1] = fmaf(vb, w0.y, db_[1]);
            da[2] = fmaf(va, w0.z, da[2]); db_[2] = fmaf(vb, w0.z, db_[2]);
            da[3] = fmaf(va, w0.w, da[3]); db_[3] = fmaf(vb, w0.w, db_[3]);
            da[4] = fmaf(va, w1.x, da[4]); db_[4] = fmaf(vb, w1.x, db_[4]);
            da[5] = fmaf(va, w1.y, da[5]); db_[5] = fmaf(vb, w1.y, db_[5]);
            da[6] = fmaf(va, w1.z, da[6]); db_[6] = fmaf(vb, w1.z, db_[6]);
            da[7] = fmaf(va, w1.w, da[7]); db_[7] = fmaf(vb, w1.w, db_[7]);
        }
        if (!GUARD || base + (2 * pp) * NTH < (unsigned)N) {
            __stcs(reinterpret_cast<float4*>(db + (2*pp) * (NTH * 32)),
                   make_float4(rr(da[0]), rr(da[1]), rr(da[2]), rr(da[3])));
            __stcs(reinterpret_cast<float4*>(db + (2*pp) * (NTH * 32) + 16),
                   make_float4(rr(da[4]), rr(da[5]), rr(da[6]), rr(da[7])));
        }
        if (!GUARD || base + (2 * pp + 1) * NTH < (unsigned)N) {
            __stcs(reinterpret_cast<float4*>(db + (2*pp+1) * (NTH * 32)),
                   make_float4(rr(db_[0]), rr(db_[1]), rr(db_[2]), rr(db_[3])));
            __stcs(reinterpret_cast<float4*>(db + (2*pp+1) * (NTH * 32) + 16),
                   make_float4(rr(db_[4]), rr(db_[5]), rr(db_[6]), rr(db_[7])));
        }
    }
}

extern "C" void kernel_launch(void* const* d_in, const int* in_sizes, int n_in,
                              void* d_out, int out_size) {
    Params P;
    for (int k = 0; k < 27; k++) P.p[k] = (const float*)d_in[k];
    int N = in_sizes[0] / 8;                 // 4194304 rows

    gather_weights<<<1, 352>>>(P);
    void* stage_ptr = nullptr;
    cudaGetSymbolAddress(&stage_ptr, g_stage);
    cudaMemcpyToSymbolAsync(c_s, stage_ptr, S_TOTAL * sizeof(float), 0,
                            cudaMemcpyDeviceToDevice, 0);

    int rows_per_block = 4 * NTH;            // 1024
    int blocks = (N + rows_per_block - 1) / rows_per_block;
    if (N % rows_per_block == 0)
        ann_fused_kernel<false><<<blocks, NTH>>>((const float*)d_in[0], (float*)d_out, N);
    else
        ann_fused_kernel<true ><<<blocks, NTH>>>((const float*)d_in[0], (float*)d_out, N);
}